// round 15
// baseline (speedup 1.0000x reference)
#include <cuda_runtime.h>
#include <cuda_fp16.h>

#define NN 50000
#define EE 800000
#define ETOT (EE + NN)          // 850000
#define FIN 128
#define HID 32
#define HEADS 4
#define F1 128                  // HEADS*HID
#define OUTC 32
#define CAP 64                  // bucket capacity per node (max degree ~36)
#define NSLOT (NN * CAP)
#define LOG2E 1.4426950408889634f

// ---- scratch (no allocs allowed) ----
__device__ __align__(16) __half g_xl1h[NN * F1];  // layer1 features (fp16)
__device__ __align__(16) __half g_h1h[NN * F1];   // elu(h1) (fp16)
__device__ __align__(16) float g_asrc1[NN * HEADS];  // pre-scaled by log2e
__device__ __align__(16) float g_adst1[NN * HEADS];
__device__ float g_xl2[NN * OUTC];
__device__ float g_asrc2[NN];                     // pre-scaled by log2e
__device__ float g_adst2[NN];
__device__ float g_part[512];
__device__ __align__(16) float g_coef1[4];        // pre-scaled by log2e
__device__ float g_coef2;
// bucketed edge store: node d owns slots [d*CAP, d*CAP+cnt[d])
__device__ int  g_cnt[NN];
__device__ __align__(16) int2  g_es2[NSLOT];      // (src, ea_bits)
__device__ __align__(16) float g_ex1f[NSLOT * 4]; // per-head ex, layer1
__device__ __align__(16) float g_ex2f[NSLOT];     // ex, layer2

#define FMA2(d, a, b) asm("fma.rn.f32x2 %0, %1, %2, %0;" : "+l"(d) : "l"(a), "l"(b))
#define EX2(r, x) asm("ex2.approx.f32 %0, %1;" : "=f"(r) : "f"(x))

// ---------------------------------------------------------------------------
// prep: zero g_cnt + easum block partials + coef dots (coefs pre-scaled)
__global__ void __launch_bounds__(256) k_prep(
    const float* __restrict__ ea,
    const float* __restrict__ l1e, const float* __restrict__ a1e,
    const float* __restrict__ l2e, const float* __restrict__ a2e) {
    int t0 = blockIdx.x * blockDim.x + threadIdx.x;
    int stride = gridDim.x * blockDim.x;   // 512*256 = 131072
    for (int i = t0; i < NN; i += stride) g_cnt[i] = 0;

    float s = 0.f;
    for (int i = t0; i < EE; i += stride) s += ea[i];
    for (int o = 16; o; o >>= 1) s += __shfl_xor_sync(0xffffffffu, s, o);
    __shared__ float sh[8];
    if ((threadIdx.x & 31) == 0) sh[threadIdx.x >> 5] = s;
    __syncthreads();
    if (threadIdx.x < 8) {
        float v = sh[threadIdx.x];
        for (int o = 4; o; o >>= 1) v += __shfl_xor_sync(0xffu, v, o);
        if (threadIdx.x == 0) g_part[blockIdx.x] = v;
    }
    if (blockIdx.x == 0 && threadIdx.x < 128) {
        int t = threadIdx.x;
        float v = l1e[t] * a1e[t];
        for (int o = 16; o; o >>= 1) v += __shfl_xor_sync(0xffffffffu, v, o);
        if ((t & 31) == 0) g_coef1[t >> 5] = v * LOG2E;
        if (t < 32) {
            float v2 = l2e[t] * a2e[t];
            for (int o = 16; o; o >>= 1) v2 += __shfl_xor_sync(0xffffffffu, v2, o);
            if (t == 0) g_coef2 = v2 * LOG2E;
        }
    }
}

// ---------------------------------------------------------------------------
// bucket scatter (atomicAdd = histogram), 4 edges/thread; late blocks also
// reduce easum partials for the self-loop fill value.
__global__ void __launch_bounds__(256) k_scatter(const int* __restrict__ eidx,
                                                 const float* __restrict__ eattr) {
    __shared__ float s_loopea;
    if ((blockIdx.x + 1) * 1024 > EE) {
        int t = threadIdx.x, lane = t & 31, w = t >> 5;
        float v = g_part[t] + g_part[t + 256];
        for (int o = 16; o; o >>= 1) v += __shfl_xor_sync(0xffffffffu, v, o);
        __shared__ float sh[8];
        if (lane == 0) sh[w] = v;
        __syncthreads();
        if (t < 8) {
            float u = sh[t];
            for (int o = 4; o; o >>= 1) u += __shfl_xor_sync(0xffu, u, o);
            if (t == 0) s_loopea = u * (1.0f / EE);
        }
        __syncthreads();
    }

    int i0 = (blockIdx.x * blockDim.x + threadIdx.x) * 4;
    if (i0 >= ETOT) return;
    if (i0 + 3 < EE) {
        int4 sv = *(const int4*)&eidx[i0];
        int4 dv = *(const int4*)&eidx[EE + i0];
        float4 av = *(const float4*)&eattr[i0];
        int p0 = atomicAdd(&g_cnt[dv.x], 1);
        int p1 = atomicAdd(&g_cnt[dv.y], 1);
        int p2 = atomicAdd(&g_cnt[dv.z], 1);
        int p3 = atomicAdd(&g_cnt[dv.w], 1);
        if (p0 < CAP) g_es2[dv.x * CAP + p0] = make_int2(sv.x, __float_as_int(av.x));
        if (p1 < CAP) g_es2[dv.y * CAP + p1] = make_int2(sv.y, __float_as_int(av.y));
        if (p2 < CAP) g_es2[dv.z * CAP + p2] = make_int2(sv.z, __float_as_int(av.z));
        if (p3 < CAP) g_es2[dv.w * CAP + p3] = make_int2(sv.w, __float_as_int(av.w));
    } else {
        #pragma unroll 1
        for (int q = 0; q < 4; q++) {
            int i = i0 + q;
            if (i >= ETOT) break;
            int s, d; float ea;
            if (i < EE) { s = eidx[i]; d = eidx[EE + i]; ea = eattr[i]; }
            else        { s = i - EE;  d = s;            ea = s_loopea; }
            int pos = atomicAdd(&g_cnt[d], 1);
            if (pos < CAP) g_es2[d * CAP + pos] = make_int2(s, __float_as_int(ea));
        }
    }
}

// ---------------------------------------------------------------------------
// xl1 = x @ W1 (128x128), f32x2 FMA, 32 nodes/block, fused attention dots
// (dots pre-scaled by log2e for exp2 downstream).
__global__ void __launch_bounds__(128) k_lin1(
    const float* __restrict__ x, const float* __restrict__ w,
    const float* __restrict__ a1s, const float* __restrict__ a1d) {
    __shared__ float sxT[FIN * 36];
    int t = threadIdx.x;
    int lane = t & 31, wid = t >> 5;
    int nbase = blockIdx.x * 32;

    #pragma unroll
    for (int jj = 0; jj < 8; jj++) {
        int j = wid * 8 + jj;
        int n = nbase + j;
        const float* xr = x + (long)min(n, NN - 1) * FIN;
        #pragma unroll
        for (int c = 0; c < 4; c++) {
            int k = c * 32 + lane;
            sxT[k * 36 + j] = (n < NN) ? xr[k] : 0.f;
        }
    }
    __syncthreads();

    unsigned long long acc[16];
    #pragma unroll
    for (int p = 0; p < 16; p++) acc[p] = 0ull;
    const int col = t;
    #pragma unroll 4
    for (int k = 0; k < FIN; k++) {
        float wv = w[k * F1 + col];
        unsigned long long wv2;
        asm("mov.b64 %0, {%1, %1};" : "=l"(wv2) : "f"(wv));
        #pragma unroll
        for (int jg = 0; jg < 8; jg++) {
            ulonglong2 xv = *(const ulonglong2*)&sxT[k * 36 + jg * 4];
            FMA2(acc[jg * 2 + 0], xv.x, wv2);
            FMA2(acc[jg * 2 + 1], xv.y, wv2);
        }
    }

    float sA = a1s[col] * LOG2E, sD = a1d[col] * LOG2E;
    #pragma unroll
    for (int p = 0; p < 16; p++) {
        float lo, hi;
        asm("mov.b64 {%0, %1}, %2;" : "=f"(lo), "=f"(hi) : "l"(acc[p]));
        int n0 = nbase + p * 2;
        if (n0 < NN)     g_xl1h[(long)n0 * F1 + col]       = __float2half_rn(lo);
        if (n0 + 1 < NN) g_xl1h[(long)(n0 + 1) * F1 + col] = __float2half_rn(hi);
        float vs0 = lo * sA, vd0 = lo * sD, vs1 = hi * sA, vd1 = hi * sD;
        #pragma unroll
        for (int o = 16; o; o >>= 1) {
            vs0 += __shfl_xor_sync(0xffffffffu, vs0, o);
            vd0 += __shfl_xor_sync(0xffffffffu, vd0, o);
            vs1 += __shfl_xor_sync(0xffffffffu, vs1, o);
            vd1 += __shfl_xor_sync(0xffffffffu, vd1, o);
        }
        if (lane == 0 && n0 < NN) {
            g_asrc1[n0 * HEADS + wid] = vs0;
            g_adst1[n0 * HEADS + wid] = vd0;
            if (n0 + 1 < NN) {
                g_asrc1[(n0 + 1) * HEADS + wid] = vs1;
                g_adst1[(n0 + 1) * HEADS + wid] = vd1;
            }
        }
    }
}

// ---------------------------------------------------------------------------
// Slot-parallel ex for layer1: all 4 heads, fp32 (bit-identical math).
__global__ void __launch_bounds__(256) k_ex1() {
    int i = blockIdx.x * blockDim.x + threadIdx.x;
    if (i >= NSLOT) return;
    int d = i >> 6;
    int pos = i & (CAP - 1);
    if (pos >= min(g_cnt[d], CAP)) return;
    int2 e = g_es2[i];
    float4 as = *(const float4*)&g_asrc1[e.x * HEADS];
    float4 ad = *(const float4*)&g_adst1[d * HEADS];
    float4 cf = *(const float4*)g_coef1;
    float ea = __int_as_float(e.y);
    float4 al;
    al.x = as.x + ad.x + ea * cf.x;
    al.y = as.y + ad.y + ea * cf.y;
    al.z = as.z + ad.z + ea * cf.z;
    al.w = as.w + ad.w + ea * cf.w;
    al.x = fmaxf(al.x, 0.2f * al.x);
    al.y = fmaxf(al.y, 0.2f * al.y);
    al.z = fmaxf(al.z, 0.2f * al.z);
    al.w = fmaxf(al.w, 0.2f * al.w);
    float4 exv;
    EX2(exv.x, al.x); EX2(exv.y, al.y);
    EX2(exv.z, al.z); EX2(exv.w, al.w);
    *(float4*)&g_ex1f[i * 4] = exv;
}

// ---------------------------------------------------------------------------
// Gather layer1: warp per dst node, x2, int4 es loads (beg even), precomputed
// ex. Epilogue: normalize+bias+ELU -> fp16 h. 512 thr = 16 nodes/block.
__global__ void __launch_bounds__(512) k_edge1(const float* __restrict__ bias1) {
    int d = blockIdx.x * 16 + (threadIdx.x >> 5);
    if (d >= NN) return;
    int l = threadIdx.x & 31;
    int h = l >> 3;
    int beg = d * CAP;
    int end = beg + min(g_cnt[d], CAP);
    float4 acc = make_float4(0.f, 0.f, 0.f, 0.f);
    float den = 0.f;
    int j = beg;
    for (; j + 2 <= end; j += 2) {
        int4 ee = *(const int4*)&g_es2[j];       // (s0, ea0, s1, ea1)
        float ex0 = g_ex1f[j * 4 + h];
        float ex1v = g_ex1f[j * 4 + 4 + h];
        uint2 p0 = *(const uint2*)(g_xl1h + (long)ee.x * F1 + l * 4);
        uint2 p1 = *(const uint2*)(g_xl1h + (long)ee.z * F1 + l * 4);
        den += ex0 + ex1v;
        float2 a0 = __half22float2(*reinterpret_cast<__half2*>(&p0.x));
        float2 b0 = __half22float2(*reinterpret_cast<__half2*>(&p0.y));
        float2 a1 = __half22float2(*reinterpret_cast<__half2*>(&p1.x));
        float2 b1 = __half22float2(*reinterpret_cast<__half2*>(&p1.y));
        acc.x += ex0 * a0.x + ex1v * a1.x;
        acc.y += ex0 * a0.y + ex1v * a1.y;
        acc.z += ex0 * b0.x + ex1v * b1.x;
        acc.w += ex0 * b0.y + ex1v * b1.y;
    }
    if (j < end) {
        int2 e0 = g_es2[j];
        float ex0 = g_ex1f[j * 4 + h];
        uint2 p0 = *(const uint2*)(g_xl1h + (long)e0.x * F1 + l * 4);
        den += ex0;
        float2 a0 = __half22float2(*reinterpret_cast<__half2*>(&p0.x));
        float2 b0 = __half22float2(*reinterpret_cast<__half2*>(&p0.y));
        acc.x += ex0 * a0.x; acc.y += ex0 * a0.y;
        acc.z += ex0 * b0.x; acc.w += ex0 * b0.y;
    }
    float inv = 1.f / den;
    float4 b = *(const float4*)&bias1[l * 4];
    float4 v;
    v.x = acc.x * inv + b.x; v.y = acc.y * inv + b.y;
    v.z = acc.z * inv + b.z; v.w = acc.w * inv + b.w;
    v.x = v.x > 0.f ? v.x : expm1f(v.x);
    v.y = v.y > 0.f ? v.y : expm1f(v.y);
    v.z = v.z > 0.f ? v.z : expm1f(v.z);
    v.w = v.w > 0.f ? v.w : expm1f(v.w);

    __half2 h01 = __floats2half2_rn(v.x, v.y);
    __half2 h23 = __floats2half2_rn(v.z, v.w);
    uint2 st;
    st.x = *reinterpret_cast<unsigned*>(&h01);
    st.y = *reinterpret_cast<unsigned*>(&h23);
    *(uint2*)(g_h1h + (long)d * F1 + l * 4) = st;
}

// ---------------------------------------------------------------------------
// xl2 = h @ W2 (128x32): register-tiled GEMM, conflict-free staging,
// fused att2 dots (log2e). 32 nodes/block, 128 threads.
__global__ void __launch_bounds__(128) k_lin2(
    const float* __restrict__ w2, const float* __restrict__ a2s,
    const float* __restrict__ a2d) {
    __shared__ float sxT[FIN * 36];   // [k][node(+pad)] of h
    int t = threadIdx.x;
    int lane = t & 31, wid = t >> 5;
    int nbase = blockIdx.x * 32;

    {
        int n = min(nbase + lane, NN - 1);
        const uint4* src = (const uint4*)(g_h1h + (long)n * F1 + wid * 32);
        #pragma unroll
        for (int q = 0; q < 4; q++) {
            uint4 u = src[q];   // 8 halves: k = wid*32 + q*8 .. +7
            int k0 = wid * 32 + q * 8;
            float2 f;
            f = __half22float2(*reinterpret_cast<__half2*>(&u.x));
            sxT[(k0 + 0) * 36 + lane] = f.x; sxT[(k0 + 1) * 36 + lane] = f.y;
            f = __half22float2(*reinterpret_cast<__half2*>(&u.y));
            sxT[(k0 + 2) * 36 + lane] = f.x; sxT[(k0 + 3) * 36 + lane] = f.y;
            f = __half22float2(*reinterpret_cast<__half2*>(&u.z));
            sxT[(k0 + 4) * 36 + lane] = f.x; sxT[(k0 + 5) * 36 + lane] = f.y;
            f = __half22float2(*reinterpret_cast<__half2*>(&u.w));
            sxT[(k0 + 6) * 36 + lane] = f.x; sxT[(k0 + 7) * 36 + lane] = f.y;
        }
    }
    __syncthreads();

    const int col = lane;
    const int jg = wid;           // node group: nodes jg*8..jg*8+7
    unsigned long long acc2[4];
    #pragma unroll
    for (int p = 0; p < 4; p++) acc2[p] = 0ull;
    #pragma unroll 4
    for (int k = 0; k < FIN; k++) {
        float wv = w2[k * OUTC + col];
        unsigned long long wv2;
        asm("mov.b64 %0, {%1, %1};" : "=l"(wv2) : "f"(wv));
        ulonglong2 xv0 = *(const ulonglong2*)&sxT[k * 36 + jg * 8];
        ulonglong2 xv1 = *(const ulonglong2*)&sxT[k * 36 + jg * 8 + 4];
        FMA2(acc2[0], xv0.x, wv2);
        FMA2(acc2[1], xv0.y, wv2);
        FMA2(acc2[2], xv1.x, wv2);
        FMA2(acc2[3], xv1.y, wv2);
    }

    float sA = a2s[col] * LOG2E, sD = a2d[col] * LOG2E;
    #pragma unroll
    for (int p = 0; p < 4; p++) {
        float lo, hi;
        asm("mov.b64 {%0, %1}, %2;" : "=f"(lo), "=f"(hi) : "l"(acc2[p]));
        int n0 = nbase + jg * 8 + p * 2;
        if (n0 < NN)     g_xl2[n0 * OUTC + col]       = lo;
        if (n0 + 1 < NN) g_xl2[(n0 + 1) * OUTC + col] = hi;
        float vs0 = lo * sA, vd0 = lo * sD, vs1 = hi * sA, vd1 = hi * sD;
        #pragma unroll
        for (int o = 16; o; o >>= 1) {
            vs0 += __shfl_xor_sync(0xffffffffu, vs0, o);
            vd0 += __shfl_xor_sync(0xffffffffu, vd0, o);
            vs1 += __shfl_xor_sync(0xffffffffu, vs1, o);
            vd1 += __shfl_xor_sync(0xffffffffu, vd1, o);
        }
        if (lane == 0 && n0 < NN) {
            g_asrc2[n0] = vs0;
            g_adst2[n0] = vd0;
            if (n0 + 1 < NN) { g_asrc2[n0 + 1] = vs1; g_adst2[n0 + 1] = vd1; }
        }
    }
}

// ---------------------------------------------------------------------------
// Slot-parallel ex for layer2 (fp32).
__global__ void __launch_bounds__(256) k_ex2() {
    int i = blockIdx.x * blockDim.x + threadIdx.x;
    if (i >= NSLOT) return;
    int d = i >> 6;
    int pos = i & (CAP - 1);
    if (pos >= min(g_cnt[d], CAP)) return;
    int2 e = g_es2[i];
    float al = g_asrc2[e.x] + g_adst2[d] + __int_as_float(e.y) * g_coef2;
    al = fmaxf(al, 0.2f * al);
    float ex; EX2(ex, al);
    g_ex2f[i] = ex;
}

// ---------------------------------------------------------------------------
// Gather layer2: warp per dst node, x2, precomputed ex (float2 loads).
__global__ void __launch_bounds__(512) k_edge2g(float* __restrict__ out,
                                                const float* __restrict__ bias2) {
    int d = blockIdx.x * 16 + (threadIdx.x >> 5);
    if (d >= NN) return;
    int l = threadIdx.x & 31;
    int beg = d * CAP;
    int end = beg + min(g_cnt[d], CAP);
    float acc = 0.f, den = 0.f;
    int j = beg;
    for (; j + 2 <= end; j += 2) {
        int4 ee = *(const int4*)&g_es2[j];
        float2 exv = *(const float2*)&g_ex2f[j];
        float v0 = g_xl2[ee.x * OUTC + l];
        float v1 = g_xl2[ee.z * OUTC + l];
        den += exv.x + exv.y;
        acc += exv.x * v0 + exv.y * v1;
    }
    if (j < end) {
        int2 e0 = g_es2[j];
        float ex0 = g_ex2f[j];
        den += ex0;
        acc += ex0 * g_xl2[e0.x * OUTC + l];
    }
    out[(long)d * OUTC + l] = acc / den + bias2[l];
}

// ---------------------------------------------------------------------------
extern "C" void kernel_launch(void* const* d_in, const int* in_sizes, int n_in,
                              void* d_out, int out_size) {
    const float* x        = (const float*)d_in[0];
    const int*   eidx     = (const int*)  d_in[1];
    const float* eattr    = (const float*)d_in[2];
    const float* lin1_w   = (const float*)d_in[3];
    const float* att1_src = (const float*)d_in[4];
    const float* att1_dst = (const float*)d_in[5];
    const float* lin1_ew  = (const float*)d_in[6];
    const float* att1_e   = (const float*)d_in[7];
    const float* bias1    = (const float*)d_in[8];
    const float* lin2_w   = (const float*)d_in[9];
    const float* att2_src = (const float*)d_in[10];
    const float* att2_dst = (const float*)d_in[11];
    const float* lin2_ew  = (const float*)d_in[12];
    const float* att2_e   = (const float*)d_in[13];
    const float* bias2    = (const float*)d_in[14];
    float* out = (float*)d_out;

    static cudaStream_t sB = nullptr;
    static cudaEvent_t evFork = nullptr, evB = nullptr;
    static bool streamsOk = false;
    if (sB == nullptr && !streamsOk) {
        bool ok = (cudaStreamCreateWithFlags(&sB, cudaStreamNonBlocking) == cudaSuccess)
               && (cudaEventCreateWithFlags(&evFork, cudaEventDisableTiming) == cudaSuccess)
               && (cudaEventCreateWithFlags(&evB, cudaEventDisableTiming) == cudaSuccess);
        streamsOk = ok;
        if (!ok) sB = nullptr;
    }

    const int exGrid = (NSLOT + 255) / 256;

    if (streamsOk) {
        // idx0: lin1 on side stream (independent of edge bucketing)
        cudaEventRecord(evFork, 0);
        cudaStreamWaitEvent(sB, evFork, 0);
        k_lin1<<<(NN + 31) / 32, 128, 0, sB>>>(x, lin1_w, att1_src, att1_dst);
        cudaEventRecord(evB, sB);

        // idx1: prep, idx2: scatter
        k_prep<<<512, 256>>>(eattr, lin1_ew, att1_e, lin2_ew, att2_e);
        k_scatter<<<(ETOT / 4 + 255) / 256, 256>>>(eidx, eattr);

        // join lin1; idx3: ex1 (profiled), idx4: edge1, idx5: lin2,
        // idx6: ex2, idx7: edge2g
        cudaStreamWaitEvent(0, evB, 0);
        k_ex1<<<exGrid, 256>>>();
        k_edge1<<<(NN + 15) / 16, 512>>>(bias1);
        k_lin2<<<(NN + 31) / 32, 128>>>(lin2_w, att2_src, att2_dst);
        k_ex2<<<exGrid, 256>>>();
        k_edge2g<<<(NN + 15) / 16, 512>>>(out, bias2);
    } else {
        // serial fallback
        k_lin1<<<(NN + 31) / 32, 128>>>(x, lin1_w, att1_src, att1_dst);
        k_prep<<<512, 256>>>(eattr, lin1_ew, att1_e, lin2_ew, att2_e);
        k_scatter<<<(ETOT / 4 + 255) / 256, 256>>>(eidx, eattr);
        k_ex1<<<exGrid, 256>>>();
        k_edge1<<<(NN + 15) / 16, 512>>>(bias1);
        k_lin2<<<(NN + 31) / 32, 128>>>(lin2_w, att2_src, att2_dst);
        k_ex2<<<exGrid, 256>>>();
        k_edge2g<<<(NN + 15) / 16, 512>>>(out, bias2);
    }
}

// round 16
// speedup vs baseline: 1.0616x; 1.0616x over previous
#include <cuda_runtime.h>
#include <cuda_fp16.h>

#define NN 50000
#define EE 800000
#define ETOT (EE + NN)          // 850000
#define FIN 128
#define HID 32
#define HEADS 4
#define F1 128                  // HEADS*HID
#define OUTC 32
#define CAP 64                  // bucket capacity per node (max degree ~36)
#define LOG2E 1.4426950408889634f

// ---- scratch (no allocs allowed) ----
__device__ __align__(16) __half g_xl1h[NN * F1];  // layer1 features (fp16)
__device__ __align__(16) __half g_h1h[NN * F1];   // elu(h1) (fp16)
__device__ __align__(16) float g_asrc1[NN * HEADS];  // pre-scaled by log2e
__device__ __align__(16) float g_adst1[NN * HEADS];
__device__ float g_xl2[NN * OUTC];
__device__ float g_asrc2[NN];                     // pre-scaled by log2e
__device__ float g_adst2[NN];
__device__ float g_part[512];
__device__ __align__(16) float g_coef1[4];        // pre-scaled by log2e
__device__ float g_coef2;
// bucketed edge store: node d owns slots [d*CAP, d*CAP+cnt[d])
__device__ int  g_cnt[NN];
__device__ __align__(16) int2 g_es2[NN * CAP];    // (src, ea_bits)

#define FMA2(d, a, b) asm("fma.rn.f32x2 %0, %1, %2, %0;" : "+l"(d) : "l"(a), "l"(b))
#define EX2(r, x) asm("ex2.approx.f32 %0, %1;" : "=f"(r) : "f"(x))

// ---------------------------------------------------------------------------
// prep: zero g_cnt + easum block partials + coef dots (coefs pre-scaled)
__global__ void __launch_bounds__(256) k_prep(
    const float* __restrict__ ea,
    const float* __restrict__ l1e, const float* __restrict__ a1e,
    const float* __restrict__ l2e, const float* __restrict__ a2e) {
    int t0 = blockIdx.x * blockDim.x + threadIdx.x;
    int stride = gridDim.x * blockDim.x;   // 512*256 = 131072
    for (int i = t0; i < NN; i += stride) g_cnt[i] = 0;

    float s = 0.f;
    for (int i = t0; i < EE; i += stride) s += ea[i];
    for (int o = 16; o; o >>= 1) s += __shfl_xor_sync(0xffffffffu, s, o);
    __shared__ float sh[8];
    if ((threadIdx.x & 31) == 0) sh[threadIdx.x >> 5] = s;
    __syncthreads();
    if (threadIdx.x < 8) {
        float v = sh[threadIdx.x];
        for (int o = 4; o; o >>= 1) v += __shfl_xor_sync(0xffu, v, o);
        if (threadIdx.x == 0) g_part[blockIdx.x] = v;
    }
    if (blockIdx.x == 0 && threadIdx.x < 128) {
        int t = threadIdx.x;
        float v = l1e[t] * a1e[t];
        for (int o = 16; o; o >>= 1) v += __shfl_xor_sync(0xffffffffu, v, o);
        if ((t & 31) == 0) g_coef1[t >> 5] = v * LOG2E;
        if (t < 32) {
            float v2 = l2e[t] * a2e[t];
            for (int o = 16; o; o >>= 1) v2 += __shfl_xor_sync(0xffffffffu, v2, o);
            if (t == 0) g_coef2 = v2 * LOG2E;
        }
    }
}

// ---------------------------------------------------------------------------
// bucket scatter (atomicAdd = histogram), 4 edges/thread; late blocks also
// reduce easum partials for the self-loop fill value.
__global__ void __launch_bounds__(256) k_scatter(const int* __restrict__ eidx,
                                                 const float* __restrict__ eattr) {
    __shared__ float s_loopea;
    if ((blockIdx.x + 1) * 1024 > EE) {
        int t = threadIdx.x, lane = t & 31, w = t >> 5;
        float v = g_part[t] + g_part[t + 256];
        for (int o = 16; o; o >>= 1) v += __shfl_xor_sync(0xffffffffu, v, o);
        __shared__ float sh[8];
        if (lane == 0) sh[w] = v;
        __syncthreads();
        if (t < 8) {
            float u = sh[t];
            for (int o = 4; o; o >>= 1) u += __shfl_xor_sync(0xffu, u, o);
            if (t == 0) s_loopea = u * (1.0f / EE);
        }
        __syncthreads();
    }

    int i0 = (blockIdx.x * blockDim.x + threadIdx.x) * 4;
    if (i0 >= ETOT) return;
    if (i0 + 3 < EE) {
        int4 sv = *(const int4*)&eidx[i0];
        int4 dv = *(const int4*)&eidx[EE + i0];
        float4 av = *(const float4*)&eattr[i0];
        int p0 = atomicAdd(&g_cnt[dv.x], 1);
        int p1 = atomicAdd(&g_cnt[dv.y], 1);
        int p2 = atomicAdd(&g_cnt[dv.z], 1);
        int p3 = atomicAdd(&g_cnt[dv.w], 1);
        if (p0 < CAP) g_es2[dv.x * CAP + p0] = make_int2(sv.x, __float_as_int(av.x));
        if (p1 < CAP) g_es2[dv.y * CAP + p1] = make_int2(sv.y, __float_as_int(av.y));
        if (p2 < CAP) g_es2[dv.z * CAP + p2] = make_int2(sv.z, __float_as_int(av.z));
        if (p3 < CAP) g_es2[dv.w * CAP + p3] = make_int2(sv.w, __float_as_int(av.w));
    } else {
        #pragma unroll 1
        for (int q = 0; q < 4; q++) {
            int i = i0 + q;
            if (i >= ETOT) break;
            int s, d; float ea;
            if (i < EE) { s = eidx[i]; d = eidx[EE + i]; ea = eattr[i]; }
            else        { s = i - EE;  d = s;            ea = s_loopea; }
            int pos = atomicAdd(&g_cnt[d], 1);
            if (pos < CAP) g_es2[d * CAP + pos] = make_int2(s, __float_as_int(ea));
        }
    }
}

// ---------------------------------------------------------------------------
// xl1 = x @ W1 (128x128), f32x2 FMA, 32 nodes/block, fused attention dots
// (dots pre-scaled by log2e for exp2 downstream).
__global__ void __launch_bounds__(128) k_lin1(
    const float* __restrict__ x, const float* __restrict__ w,
    const float* __restrict__ a1s, const float* __restrict__ a1d) {
    __shared__ float sxT[FIN * 36];
    int t = threadIdx.x;
    int lane = t & 31, wid = t >> 5;
    int nbase = blockIdx.x * 32;

    #pragma unroll
    for (int jj = 0; jj < 8; jj++) {
        int j = wid * 8 + jj;
        int n = nbase + j;
        const float* xr = x + (long)min(n, NN - 1) * FIN;
        #pragma unroll
        for (int c = 0; c < 4; c++) {
            int k = c * 32 + lane;
            sxT[k * 36 + j] = (n < NN) ? xr[k] : 0.f;
        }
    }
    __syncthreads();

    unsigned long long acc[16];
    #pragma unroll
    for (int p = 0; p < 16; p++) acc[p] = 0ull;
    const int col = t;
    #pragma unroll 4
    for (int k = 0; k < FIN; k++) {
        float wv = w[k * F1 + col];
        unsigned long long wv2;
        asm("mov.b64 %0, {%1, %1};" : "=l"(wv2) : "f"(wv));
        #pragma unroll
        for (int jg = 0; jg < 8; jg++) {
            ulonglong2 xv = *(const ulonglong2*)&sxT[k * 36 + jg * 4];
            FMA2(acc[jg * 2 + 0], xv.x, wv2);
            FMA2(acc[jg * 2 + 1], xv.y, wv2);
        }
    }

    float sA = a1s[col] * LOG2E, sD = a1d[col] * LOG2E;
    #pragma unroll
    for (int p = 0; p < 16; p++) {
        float lo, hi;
        asm("mov.b64 {%0, %1}, %2;" : "=f"(lo), "=f"(hi) : "l"(acc[p]));
        int n0 = nbase + p * 2;
        if (n0 < NN)     g_xl1h[(long)n0 * F1 + col]       = __float2half_rn(lo);
        if (n0 + 1 < NN) g_xl1h[(long)(n0 + 1) * F1 + col] = __float2half_rn(hi);
        float vs0 = lo * sA, vd0 = lo * sD, vs1 = hi * sA, vd1 = hi * sD;
        #pragma unroll
        for (int o = 16; o; o >>= 1) {
            vs0 += __shfl_xor_sync(0xffffffffu, vs0, o);
            vd0 += __shfl_xor_sync(0xffffffffu, vd0, o);
            vs1 += __shfl_xor_sync(0xffffffffu, vs1, o);
            vd1 += __shfl_xor_sync(0xffffffffu, vd1, o);
        }
        if (lane == 0 && n0 < NN) {
            g_asrc1[n0 * HEADS + wid] = vs0;
            g_adst1[n0 * HEADS + wid] = vd0;
            if (n0 + 1 < NN) {
                g_asrc1[(n0 + 1) * HEADS + wid] = vs1;
                g_adst1[(n0 + 1) * HEADS + wid] = vd1;
            }
        }
    }
}

// ---------------------------------------------------------------------------
// Gather layer1: warp per dst node, 8-edge groups. Lane l computes ex for
// edge (l&7), head (l>>3) — no redundant alpha math. den via 3-step xor
// butterfly within the 8-lane head group; per-edge s/ex via 2 shuffles.
// Epilogue: normalize+bias+ELU -> fp16 h. 512 thr = 16 nodes/block.
__global__ void __launch_bounds__(512) k_edge1(const float* __restrict__ bias1) {
    int d = blockIdx.x * 16 + (threadIdx.x >> 5);
    if (d >= NN) return;
    int l = threadIdx.x & 31;
    int e = l & 7, h = l >> 3;
    int lbase = l & 24;           // head-group base lane (h*8)
    int beg = d * CAP;
    int end = beg + min(g_cnt[d], CAP);
    float adst = g_adst1[d * HEADS + h];
    float cf = g_coef1[h];
    float4 acc = make_float4(0.f, 0.f, 0.f, 0.f);
    float den = 0.f;

    int j = beg;
    for (; j + 8 <= end; j += 8) {
        int2 ee = g_es2[j + e];                    // this lane's edge
        float as = g_asrc1[ee.x * HEADS + h];
        float al = as + adst + __int_as_float(ee.y) * cf;
        al = fmaxf(al, 0.2f * al);
        float ex; EX2(ex, al);
        // den: sum of 8 ex within the head group
        float ds = ex;
        ds += __shfl_xor_sync(0xffffffffu, ds, 1);
        ds += __shfl_xor_sync(0xffffffffu, ds, 2);
        ds += __shfl_xor_sync(0xffffffffu, ds, 4);
        den += ds;
        // feature accumulation: broadcast (s, ex) of each edge from head group
        #pragma unroll
        for (int q = 0; q < 8; q++) {
            int sq   = __shfl_sync(0xffffffffu, ee.x, lbase + q);
            float xq = __shfl_sync(0xffffffffu, ex,   lbase + q);
            uint2 p = *(const uint2*)(g_xl1h + (long)sq * F1 + l * 4);
            float2 a = __half22float2(*reinterpret_cast<__half2*>(&p.x));
            float2 b = __half22float2(*reinterpret_cast<__half2*>(&p.y));
            acc.x += xq * a.x; acc.y += xq * a.y;
            acc.z += xq * b.x; acc.w += xq * b.y;
        }
    }
    // tail (<8 edges): inline alpha per edge (proven R13 code)
    #pragma unroll 1
    for (; j < end; j++) {
        int2 e0 = g_es2[j];
        float as0 = g_asrc1[e0.x * HEADS + h];
        uint2 p0 = *(const uint2*)(g_xl1h + (long)e0.x * F1 + l * 4);
        float al0 = as0 + adst + __int_as_float(e0.y) * cf;
        al0 = fmaxf(al0, 0.2f * al0);
        float ex0; EX2(ex0, al0);
        den += ex0;
        float2 a0 = __half22float2(*reinterpret_cast<__half2*>(&p0.x));
        float2 b0 = __half22float2(*reinterpret_cast<__half2*>(&p0.y));
        acc.x += ex0 * a0.x; acc.y += ex0 * a0.y;
        acc.z += ex0 * b0.x; acc.w += ex0 * b0.y;
    }

    float inv = 1.f / den;
    float4 b = *(const float4*)&bias1[l * 4];
    float4 v;
    v.x = acc.x * inv + b.x; v.y = acc.y * inv + b.y;
    v.z = acc.z * inv + b.z; v.w = acc.w * inv + b.w;
    v.x = v.x > 0.f ? v.x : expm1f(v.x);
    v.y = v.y > 0.f ? v.y : expm1f(v.y);
    v.z = v.z > 0.f ? v.z : expm1f(v.z);
    v.w = v.w > 0.f ? v.w : expm1f(v.w);

    __half2 h01 = __floats2half2_rn(v.x, v.y);
    __half2 h23 = __floats2half2_rn(v.z, v.w);
    uint2 st;
    st.x = *reinterpret_cast<unsigned*>(&h01);
    st.y = *reinterpret_cast<unsigned*>(&h23);
    *(uint2*)(g_h1h + (long)d * F1 + l * 4) = st;
}

// ---------------------------------------------------------------------------
// xl2 = h @ W2 (128x32): register-tiled GEMM, conflict-free staging,
// fused att2 dots (log2e). 32 nodes/block, 128 threads.
__global__ void __launch_bounds__(128) k_lin2(
    const float* __restrict__ w2, const float* __restrict__ a2s,
    const float* __restrict__ a2d) {
    __shared__ float sxT[FIN * 36];   // [k][node(+pad)] of h
    int t = threadIdx.x;
    int lane = t & 31, wid = t >> 5;
    int nbase = blockIdx.x * 32;

    {
        int n = min(nbase + lane, NN - 1);
        const uint4* src = (const uint4*)(g_h1h + (long)n * F1 + wid * 32);
        #pragma unroll
        for (int q = 0; q < 4; q++) {
            uint4 u = src[q];   // 8 halves: k = wid*32 + q*8 .. +7
            int k0 = wid * 32 + q * 8;
            float2 f;
            f = __half22float2(*reinterpret_cast<__half2*>(&u.x));
            sxT[(k0 + 0) * 36 + lane] = f.x; sxT[(k0 + 1) * 36 + lane] = f.y;
            f = __half22float2(*reinterpret_cast<__half2*>(&u.y));
            sxT[(k0 + 2) * 36 + lane] = f.x; sxT[(k0 + 3) * 36 + lane] = f.y;
            f = __half22float2(*reinterpret_cast<__half2*>(&u.z));
            sxT[(k0 + 4) * 36 + lane] = f.x; sxT[(k0 + 5) * 36 + lane] = f.y;
            f = __half22float2(*reinterpret_cast<__half2*>(&u.w));
            sxT[(k0 + 6) * 36 + lane] = f.x; sxT[(k0 + 7) * 36 + lane] = f.y;
        }
    }
    __syncthreads();

    const int col = lane;
    const int jg = wid;           // node group: nodes jg*8..jg*8+7
    unsigned long long acc2[4];
    #pragma unroll
    for (int p = 0; p < 4; p++) acc2[p] = 0ull;
    #pragma unroll 4
    for (int k = 0; k < FIN; k++) {
        float wv = w2[k * OUTC + col];
        unsigned long long wv2;
        asm("mov.b64 %0, {%1, %1};" : "=l"(wv2) : "f"(wv));
        ulonglong2 xv0 = *(const ulonglong2*)&sxT[k * 36 + jg * 8];
        ulonglong2 xv1 = *(const ulonglong2*)&sxT[k * 36 + jg * 8 + 4];
        FMA2(acc2[0], xv0.x, wv2);
        FMA2(acc2[1], xv0.y, wv2);
        FMA2(acc2[2], xv1.x, wv2);
        FMA2(acc2[3], xv1.y, wv2);
    }

    float sA = a2s[col] * LOG2E, sD = a2d[col] * LOG2E;
    #pragma unroll
    for (int p = 0; p < 4; p++) {
        float lo, hi;
        asm("mov.b64 {%0, %1}, %2;" : "=f"(lo), "=f"(hi) : "l"(acc2[p]));
        int n0 = nbase + jg * 8 + p * 2;
        if (n0 < NN)     g_xl2[n0 * OUTC + col]       = lo;
        if (n0 + 1 < NN) g_xl2[(n0 + 1) * OUTC + col] = hi;
        float vs0 = lo * sA, vd0 = lo * sD, vs1 = hi * sA, vd1 = hi * sD;
        #pragma unroll
        for (int o = 16; o; o >>= 1) {
            vs0 += __shfl_xor_sync(0xffffffffu, vs0, o);
            vd0 += __shfl_xor_sync(0xffffffffu, vd0, o);
            vs1 += __shfl_xor_sync(0xffffffffu, vs1, o);
            vd1 += __shfl_xor_sync(0xffffffffu, vd1, o);
        }
        if (lane == 0 && n0 < NN) {
            g_asrc2[n0] = vs0;
            g_adst2[n0] = vd0;
            if (n0 + 1 < NN) { g_asrc2[n0 + 1] = vs1; g_adst2[n0 + 1] = vd1; }
        }
    }
}

// ---------------------------------------------------------------------------
// Gather layer2: warp per dst node, 16-edge groups. Lane l computes ex for
// edge (l&15) (both warp halves duplicate, so 4-step xor butterfly gives the
// 16-edge sum everywhere); per-edge s/ex via 2 shuffles; lane = out col.
__global__ void __launch_bounds__(512) k_edge2g(float* __restrict__ out,
                                                const float* __restrict__ bias2) {
    int d = blockIdx.x * 16 + (threadIdx.x >> 5);
    if (d >= NN) return;
    int l = threadIdx.x & 31;
    int e = l & 15;
    int lbase = l & 16;
    int beg = d * CAP;
    int end = beg + min(g_cnt[d], CAP);
    float adst = g_adst2[d];
    float cf = g_coef2;
    float acc = 0.f, den = 0.f;

    int j = beg;
    for (; j + 16 <= end; j += 16) {
        int2 ee = g_es2[j + e];
        float al = g_asrc2[ee.x] + adst + __int_as_float(ee.y) * cf;
        al = fmaxf(al, 0.2f * al);
        float ex; EX2(ex, al);
        float ds = ex;
        ds += __shfl_xor_sync(0xffffffffu, ds, 1);
        ds += __shfl_xor_sync(0xffffffffu, ds, 2);
        ds += __shfl_xor_sync(0xffffffffu, ds, 4);
        ds += __shfl_xor_sync(0xffffffffu, ds, 8);
        den += ds;
        #pragma unroll
        for (int q = 0; q < 16; q++) {
            int sq   = __shfl_sync(0xffffffffu, ee.x, lbase + q);
            float xq = __shfl_sync(0xffffffffu, ex,   lbase + q);
            acc += xq * g_xl2[sq * OUTC + l];
        }
    }
    // tail (<16 edges): inline alpha per edge
    #pragma unroll 1
    for (; j < end; j++) {
        int2 e0 = g_es2[j];
        float al0 = g_asrc2[e0.x] + adst + __int_as_float(e0.y) * cf;
        al0 = fmaxf(al0, 0.2f * al0);
        float ex0; EX2(ex0, al0);
        den += ex0;
        acc += ex0 * g_xl2[e0.x * OUTC + l];
    }
    out[(long)d * OUTC + l] = acc / den + bias2[l];
}

// ---------------------------------------------------------------------------
extern "C" void kernel_launch(void* const* d_in, const int* in_sizes, int n_in,
                              void* d_out, int out_size) {
    const float* x        = (const float*)d_in[0];
    const int*   eidx     = (const int*)  d_in[1];
    const float* eattr    = (const float*)d_in[2];
    const float* lin1_w   = (const float*)d_in[3];
    const float* att1_src = (const float*)d_in[4];
    const float* att1_dst = (const float*)d_in[5];
    const float* lin1_ew  = (const float*)d_in[6];
    const float* att1_e   = (const float*)d_in[7];
    const float* bias1    = (const float*)d_in[8];
    const float* lin2_w   = (const float*)d_in[9];
    const float* att2_src = (const float*)d_in[10];
    const float* att2_dst = (const float*)d_in[11];
    const float* lin2_ew  = (const float*)d_in[12];
    const float* att2_e   = (const float*)d_in[13];
    const float* bias2    = (const float*)d_in[14];
    float* out = (float*)d_out;

    static cudaStream_t sB = nullptr;
    static cudaEvent_t evFork = nullptr, evB = nullptr;
    static bool streamsOk = false;
    if (sB == nullptr && !streamsOk) {
        bool ok = (cudaStreamCreateWithFlags(&sB, cudaStreamNonBlocking) == cudaSuccess)
               && (cudaEventCreateWithFlags(&evFork, cudaEventDisableTiming) == cudaSuccess)
               && (cudaEventCreateWithFlags(&evB, cudaEventDisableTiming) == cudaSuccess);
        streamsOk = ok;
        if (!ok) sB = nullptr;
    }

    if (streamsOk) {
        // idx0: lin1 on side stream (independent of edge bucketing)
        cudaEventRecord(evFork, 0);
        cudaStreamWaitEvent(sB, evFork, 0);
        k_lin1<<<(NN + 31) / 32, 128, 0, sB>>>(x, lin1_w, att1_src, att1_dst);
        cudaEventRecord(evB, sB);

        // idx1: prep, idx2: scatter
        k_prep<<<512, 256>>>(eattr, lin1_ew, att1_e, lin2_ew, att2_e);
        k_scatter<<<(ETOT / 4 + 255) / 256, 256>>>(eidx, eattr);

        // idx3: edge1 (ncu -s5 profiles this), idx4: lin2, idx5: edge2g
        cudaStreamWaitEvent(0, evB, 0);
        k_edge1<<<(NN + 15) / 16, 512>>>(bias1);
        k_lin2<<<(NN + 31) / 32, 128>>>(lin2_w, att2_src, att2_dst);
        k_edge2g<<<(NN + 15) / 16, 512>>>(out, bias2);
    } else {
        // serial fallback
        k_lin1<<<(NN + 31) / 32, 128>>>(x, lin1_w, att1_src, att1_dst);
        k_prep<<<512, 256>>>(eattr, lin1_ew, att1_e, lin2_ew, att2_e);
        k_scatter<<<(ETOT / 4 + 255) / 256, 256>>>(eidx, eattr);
        k_edge1<<<(NN + 15) / 16, 512>>>(bias1);
        k_lin2<<<(NN + 31) / 32, 128>>>(lin2_w, att2_src, att2_dst);
        k_edge2g<<<(NN + 15) / 16, 512>>>(out, bias2);
    }
}